// round 11
// baseline (speedup 1.0000x reference)
#include <cuda_runtime.h>
#include <cstddef>
#include <cstdint>

// Problem constants (fixed by the reference)
#define NNODES 100000
#define EMAX   1600000
#define FDIM   128

typedef unsigned long long ull;

// ---------------- scratch (static device globals; no runtime alloc) ----------------
__device__ int   g_is64;                   // edge_index dtype flag (1 = int64)
__device__ int   g_src[EMAX];              // decoded src indices (int32)
__device__ int   g_dst[EMAX];              // decoded dst indices (int32)
__device__ int   g_deg[NNODES];            // in-degree incl. self loop
__device__ float g_dinv[NNODES];           // deg^-1/2
__device__ int   g_rowptr[NNODES];         // CSR row start (real edges only)
__device__ int   g_cursor[NNODES];         // scatter cursors
__device__ int   g_col[EMAX];              // CSR column (src) per edge
__device__ int   g_bsums[128];             // block sums for scan
__device__ float g_h[(size_t)NNODES * FDIM];   // per-layer GEMM output (pre-scaled by dinv)
__device__ float g_x[(size_t)NNODES * FDIM];   // per-layer activation ping buffer

// ---------------- packed f32x2 helpers (Blackwell FFMA2 path, works on sm_100) ----------------

__device__ __forceinline__ void ffma2(ull& d, ull a, ull b) {
    asm("fma.rn.f32x2 %0, %1, %2, %0;" : "+l"(d) : "l"(a), "l"(b));
}

__device__ __forceinline__ ull pack2(float x) {
    ull r;
    unsigned xi = __float_as_uint(x);
    asm("mov.b64 %0, {%1, %1};" : "=l"(r) : "r"(xi));
    return r;
}

__device__ __forceinline__ float2 unpack2(ull v) {
    unsigned lo, hi;
    asm("mov.b64 {%0, %1}, %2;" : "=r"(lo), "=r"(hi) : "l"(v));
    return make_float2(__uint_as_float(lo), __uint_as_float(hi));
}

// ---------------- edge dtype detect + decode+hist ----------------

__global__ void k_detect(const int* __restrict__ ei32) {
    __shared__ int nz;
    if (threadIdx.x == 0) nz = 0;
    __syncthreads();
    for (int i = threadIdx.x; i < 4096; i += 256)
        if (ei32[2 * i + 1] != 0) atomicAdd(&nz, 1);
    __syncthreads();
    if (threadIdx.x == 0) g_is64 = (nz == 0) ? 1 : 0;
}

__global__ void k_init_deg(int n) {
    int i = blockIdx.x * blockDim.x + threadIdx.x;
    if (i < n) g_deg[i] = 1;  // self loop
}

__global__ void k_decode_hist(const void* __restrict__ ei, int e) {
    int i = blockIdx.x * blockDim.x + threadIdx.x;
    if (i >= e) return;
    int s, d;
    if (g_is64) {
        const long long* p = (const long long*)ei;
        s = (int)p[i];
        d = (int)p[(size_t)e + i];
    } else {
        const int* p = (const int*)ei;
        s = p[i];
        d = p[(size_t)e + i];
    }
    g_src[i] = s;
    g_dst[i] = d;
    if ((unsigned)d < NNODES) atomicAdd(&g_deg[d], 1);
}

// ---------------- CSR build ----------------

__global__ void k_scan_block(int n) {
    __shared__ int s[1024];
    int i = blockIdx.x * 1024 + threadIdx.x;
    int v = (i < n) ? (g_deg[i] - 1) : 0;
    s[threadIdx.x] = v;
    __syncthreads();
    for (int off = 1; off < 1024; off <<= 1) {
        int t = (threadIdx.x >= off) ? s[threadIdx.x - off] : 0;
        __syncthreads();
        s[threadIdx.x] += t;
        __syncthreads();
    }
    if (i < n) g_rowptr[i] = s[threadIdx.x] - v;
    if (threadIdx.x == 1023) g_bsums[blockIdx.x] = s[1023];
}

__global__ void k_scan_bsums(int nb) {
    __shared__ int s[128];
    int t = threadIdx.x;
    int v = (t < nb) ? g_bsums[t] : 0;
    s[t] = v;
    __syncthreads();
    for (int off = 1; off < 128; off <<= 1) {
        int u = (t >= off) ? s[t - off] : 0;
        __syncthreads();
        s[t] += u;
        __syncthreads();
    }
    g_bsums[t] = s[t] - v;
}

__global__ void k_add_off(int n) {
    int i = blockIdx.x * blockDim.x + threadIdx.x;
    if (i < n) {
        int rp = g_rowptr[i] + g_bsums[i >> 10];
        g_rowptr[i] = rp;
        g_cursor[i] = rp;
        g_dinv[i] = rsqrtf((float)g_deg[i]);
    }
}

__global__ void k_scatter(int e) {
    int i = blockIdx.x * blockDim.x + threadIdx.x;
    if (i < e) {
        unsigned s = (unsigned)g_src[i];
        unsigned d = (unsigned)g_dst[i];
        if (s < NNODES && d < NNODES) {
            int pos = atomicAdd(&g_cursor[d], 1);
            if (pos >= 0 && pos < EMAX) g_col[pos] = (int)s;
        }
    }
}

// ---------------- GEMM: g_h[n,FO] = dinv[row] * (X[n,128] * W[128,FO]) ----------------
// 256 threads, 64-row tile, K-tiled (KC=16). Row-pair FFMA2 formulation:
// acc[col] holds {acc_row_even, acc_row_odd}; x-pair comes from a TRANSPOSED
// X tile (one LDS.64, no packing movs); w is pre-duplicated {w,w} in smem.
// Per k per thread: 2 LDS.128 (w) + 4 x (LDS.64 + 4 FFMA2) = 22 slots / 16 FFMA2.
template <int FO, bool X_FROM_G>
__global__ void __launch_bounds__(256) k_gemm(const float* __restrict__ Xin,
                                              const float* __restrict__ W, int n) {
    constexpr int TR  = 64;
    constexpr int KC  = 16;         // k-chunk
    constexpr int CPT = FO / 4;     // threads covering the column dim (4 cols each)
    constexpr int G   = 256 / CPT;  // row groups
    constexpr int RPT = TR / G;     // rows per thread
    constexpr int NP  = RPT / 2;    // row pairs per thread

    __shared__ float Xt[128 * TR];  // transposed X tile: Xt[k][r], 32 KB
    __shared__ ull   Wd[KC * FO];   // duplicated W chunk: {w,w}, 16 KB (FO=128) / 8 KB

    const float* X = X_FROM_G ? g_x : Xin;
    float* H = g_h;

    int row0 = blockIdx.x * TR;

    // Transposed X load. Mapping i -> (c4 = i>>6, r = i&63): lanes of a warp share
    // c4 and have consecutive r, so each of the 4 STS streams is conflict-free.
    for (int i = threadIdx.x; i < TR * 32; i += 256) {
        int c4 = i >> 6;            // float4 column index 0..31
        int r  = i & 63;
        float4 v = make_float4(0.f, 0.f, 0.f, 0.f);
        if (row0 + r < n)
            v = reinterpret_cast<const float4*>(X + (size_t)(row0 + r) * 128)[c4];
        Xt[(c4 * 4 + 0) * TR + r] = v.x;
        Xt[(c4 * 4 + 1) * TR + r] = v.y;
        Xt[(c4 * 4 + 2) * TR + r] = v.z;
        Xt[(c4 * 4 + 3) * TR + r] = v.w;
    }

    int cq = threadIdx.x % CPT;     // column quad index (4 cols)
    int g  = threadIdx.x / CPT;
    int r0 = g * RPT;               // even

    ull acc[4][NP];
#pragma unroll
    for (int c = 0; c < 4; c++)
#pragma unroll
        for (int p = 0; p < NP; p++) acc[c][p] = 0ull;

    for (int kc = 0; kc < 128 / KC; kc++) {
        __syncthreads();  // previous Wd readers done (and Xt ready on iter 0)
        for (int i = threadIdx.x; i < KC * FO; i += 256) {
            int k = i / FO, c = i % FO;
            Wd[i] = pack2(W[(size_t)(kc * KC + k) * FO + c]);
        }
        __syncthreads();

#pragma unroll
        for (int k = 0; k < KC; k++) {
            const ull* wrow = &Wd[k * FO + cq * 4];
            ulonglong2 wa = *reinterpret_cast<const ulonglong2*>(wrow);
            ulonglong2 wb = *reinterpret_cast<const ulonglong2*>(wrow + 2);
            const float* xcol = &Xt[(kc * KC + k) * TR + r0];
#pragma unroll
            for (int p = 0; p < NP; p++) {
                ull xp = *reinterpret_cast<const ull*>(xcol + 2 * p);  // {x_even, x_odd}
                ffma2(acc[0][p], xp, wa.x);
                ffma2(acc[1][p], xp, wa.y);
                ffma2(acc[2][p], xp, wb.x);
                ffma2(acc[3][p], xp, wb.y);
            }
        }
    }

    // Epilogue: unzip row pairs, scale by dinv[row], write float4 per row.
#pragma unroll
    for (int p = 0; p < NP; p++) {
        float2 c0 = unpack2(acc[0][p]);
        float2 c1 = unpack2(acc[1][p]);
        float2 c2 = unpack2(acc[2][p]);
        float2 c3 = unpack2(acc[3][p]);
        int row_e = row0 + r0 + 2 * p;
        int row_o = row_e + 1;
        if (row_e < n) {
            float dv = g_dinv[row_e];
            float4 v = make_float4(c0.x * dv, c1.x * dv, c2.x * dv, c3.x * dv);
            reinterpret_cast<float4*>(H + (size_t)row_e * FO)[cq] = v;
        }
        if (row_o < n) {
            float dv = g_dinv[row_o];
            float4 v = make_float4(c0.y * dv, c1.y * dv, c2.y * dv, c3.y * dv);
            reinterpret_cast<float4*>(H + (size_t)row_o * FO)[cq] = v;
        }
    }
}

// ---------------- Aggregation ----------------
// H is pre-scaled: H'[v] = dinv[v] * (X W)[v].
// out[v] = relu( dinv[v] * (H'[v] + sum_{e: dst=v} H'[src_e]) + b )
template <int FO, bool OUT_TO_G>
__global__ void k_agg(const float* __restrict__ b, float* __restrict__ out_ext, int n) {
    int node = (blockIdx.x * blockDim.x + threadIdx.x) >> 5;
    if (node >= n) return;
    int lane = threadIdx.x & 31;
    constexpr int V = FO / 32;
    int f0 = lane * V;

    const float* H = g_h;
    float* out = OUT_TO_G ? g_x : out_ext;

    float dv = g_dinv[node];
    float acc[V];
    {
        const float* hr = H + (size_t)node * FO + f0;
        if (V == 4) {
            float4 hv = *reinterpret_cast<const float4*>(hr);
            acc[0] = hv.x; acc[1] = hv.y; acc[2] = hv.z; acc[3] = hv.w;
        } else {
            float2 hv = *reinterpret_cast<const float2*>(hr);
            acc[0] = hv.x; acc[1] = hv.y;
        }
    }

    int beg = g_rowptr[node];
    int end = beg + (g_deg[node] - 1);
    int e = beg;
    for (; e + 3 < end; e += 4) {
        int s0 = g_col[e], s1 = g_col[e + 1], s2 = g_col[e + 2], s3 = g_col[e + 3];
        const float* h0 = H + (size_t)s0 * FO + f0;
        const float* h1 = H + (size_t)s1 * FO + f0;
        const float* h2 = H + (size_t)s2 * FO + f0;
        const float* h3 = H + (size_t)s3 * FO + f0;
        if (V == 4) {
            float4 a = *reinterpret_cast<const float4*>(h0);
            float4 c = *reinterpret_cast<const float4*>(h1);
            float4 d = *reinterpret_cast<const float4*>(h2);
            float4 f = *reinterpret_cast<const float4*>(h3);
            acc[0] += (a.x + c.x) + (d.x + f.x);
            acc[1] += (a.y + c.y) + (d.y + f.y);
            acc[2] += (a.z + c.z) + (d.z + f.z);
            acc[3] += (a.w + c.w) + (d.w + f.w);
        } else {
            float2 a = *reinterpret_cast<const float2*>(h0);
            float2 c = *reinterpret_cast<const float2*>(h1);
            float2 d = *reinterpret_cast<const float2*>(h2);
            float2 f = *reinterpret_cast<const float2*>(h3);
            acc[0] += (a.x + c.x) + (d.x + f.x);
            acc[1] += (a.y + c.y) + (d.y + f.y);
        }
    }
    for (; e < end; e++) {
        int s0 = g_col[e];
        const float* h0 = H + (size_t)s0 * FO + f0;
        if (V == 4) {
            float4 a = *reinterpret_cast<const float4*>(h0);
            acc[0] += a.x; acc[1] += a.y; acc[2] += a.z; acc[3] += a.w;
        } else {
            float2 a = *reinterpret_cast<const float2*>(h0);
            acc[0] += a.x; acc[1] += a.y;
        }
    }

    float* orow = out + (size_t)node * FO + f0;
    if (V == 4) {
        float4 v;
        v.x = fmaxf(acc[0] * dv + b[f0 + 0], 0.f);
        v.y = fmaxf(acc[1] * dv + b[f0 + 1], 0.f);
        v.z = fmaxf(acc[2] * dv + b[f0 + 2], 0.f);
        v.w = fmaxf(acc[3] * dv + b[f0 + 3], 0.f);
        *reinterpret_cast<float4*>(orow) = v;
    } else {
        float2 v;
        v.x = fmaxf(acc[0] * dv + b[f0 + 0], 0.f);
        v.y = fmaxf(acc[1] * dv + b[f0 + 1], 0.f);
        *reinterpret_cast<float2*>(orow) = v;
    }
}

// ---------------- launch ----------------

extern "C" void kernel_launch(void* const* d_in, const int* in_sizes, int n_in,
                              void* d_out, int out_size) {
    // Classify inputs by element count — robust to metadata ordering.
    const float* x  = nullptr;
    const void*  ei = nullptr;
    const float* W[4] = {nullptr, nullptr, nullptr, nullptr};
    const float* B[4] = {nullptr, nullptr, nullptr, nullptr};
    int nw = 0, nb_ = 0;
    for (int i = 0; i < n_in; i++) {
        int sz = in_sizes[i];
        if (sz == NNODES * FDIM)       x = (const float*)d_in[i];
        else if (sz == 2 * EMAX)       ei = d_in[i];
        else if (sz == 128 * 128)      { if (nw < 3) W[nw++] = (const float*)d_in[i]; }
        else if (sz == 128 * 64)       W[3] = (const float*)d_in[i];
        else if (sz == 128)            { if (nb_ < 3) B[nb_++] = (const float*)d_in[i]; }
        else if (sz == 64)             B[3] = (const float*)d_in[i];
    }

    const int n = NNODES;
    const int E = EMAX;
    float* Obuf = (float*)d_out;

    // ---- CSR build ----
    k_detect<<<1, 256>>>((const int*)ei);
    k_init_deg<<<(n + 255) / 256, 256>>>(n);
    k_decode_hist<<<(E + 255) / 256, 256>>>(ei, E);
    int nblk = (n + 1023) / 1024;
    k_scan_block<<<nblk, 1024>>>(n);
    k_scan_bsums<<<1, 128>>>(nblk);
    k_add_off<<<(n + 255) / 256, 256>>>(n);
    k_scatter<<<(E + 255) / 256, 256>>>(E);

    // ---- layers ----
    const int gemm_blocks = (n + 63) / 64;
    const int agg_blocks  = (n * 32 + 255) / 256;

    // L0: x -> g_h -> g_x
    k_gemm<128, false><<<gemm_blocks, 256>>>(x, W[0], n);
    k_agg<128, true><<<agg_blocks, 256>>>(B[0], Obuf, n);
    // L1
    k_gemm<128, true><<<gemm_blocks, 256>>>(x, W[1], n);
    k_agg<128, true><<<agg_blocks, 256>>>(B[1], Obuf, n);
    // L2
    k_gemm<128, true><<<gemm_blocks, 256>>>(x, W[2], n);
    k_agg<128, true><<<agg_blocks, 256>>>(B[2], Obuf, n);
    // L3: 128 -> 64, write straight to d_out
    k_gemm<64, true><<<gemm_blocks, 256>>>(x, W[3], n);
    k_agg<64, false><<<agg_blocks, 256>>>(B[3], Obuf, n);
}

// round 12
// speedup vs baseline: 1.3509x; 1.3509x over previous
#include <cuda_runtime.h>
#include <cstddef>
#include <cstdint>

// Problem constants (fixed by the reference)
#define NNODES 100000
#define EMAX   1600000
#define FDIM   128

typedef unsigned long long ull;

// ---------------- scratch (static device globals; no runtime alloc) ----------------
__device__ int   g_is64;                   // edge_index dtype flag (1 = int64)
__device__ int   g_src[EMAX];              // decoded src indices (int32)
__device__ int   g_dst[EMAX];              // decoded dst indices (int32)
__device__ int   g_deg[NNODES];            // in-degree incl. self loop
__device__ float g_dinv[NNODES];           // deg^-1/2
__device__ int   g_rowptr[NNODES];         // CSR row start (real edges only)
__device__ int   g_cursor[NNODES];         // scatter cursors
__device__ int   g_col[EMAX];              // CSR column (src) per edge
__device__ int   g_bsums[128];             // block sums for scan
__device__ float g_h[(size_t)NNODES * FDIM];   // per-layer GEMM output (pre-scaled by dinv)
__device__ float g_x[(size_t)NNODES * FDIM];   // per-layer activation ping buffer

// ---------------- packed f32x2 helpers (FFMA2 path, works on sm_100) ----------------

__device__ __forceinline__ void ffma2(ull& d, ull a, ull b) {
    asm("fma.rn.f32x2 %0, %1, %2, %0;" : "+l"(d) : "l"(a), "l"(b));
}

__device__ __forceinline__ ull pack2(float x) {
    ull r;
    unsigned xi = __float_as_uint(x);
    asm("mov.b64 %0, {%1, %1};" : "=l"(r) : "r"(xi));
    return r;
}

__device__ __forceinline__ float2 unpack2(ull v) {
    unsigned lo, hi;
    asm("mov.b64 {%0, %1}, %2;" : "=r"(lo), "=r"(hi) : "l"(v));
    return make_float2(__uint_as_float(lo), __uint_as_float(hi));
}

// ---------------- CSR build (merged kernels) ----------------

// init deg=1 everywhere; block 0 also detects edge dtype.
__global__ void k_init_detect(const int* __restrict__ ei32, int n) {
    __shared__ int nz;
    int i = blockIdx.x * blockDim.x + threadIdx.x;
    if (i < n) g_deg[i] = 1;  // self loop
    if (blockIdx.x == 0) {
        if (threadIdx.x == 0) nz = 0;
        __syncthreads();
        for (int j = threadIdx.x; j < 4096; j += 256)
            if (ei32[2 * j + 1] != 0) atomicAdd(&nz, 1);
        __syncthreads();
        if (threadIdx.x == 0) g_is64 = (nz == 0) ? 1 : 0;
    }
}

// Decode edge indices (int32 or int64) AND histogram dst degrees in one pass.
__global__ void k_decode_hist(const void* __restrict__ ei, int e) {
    int i = blockIdx.x * blockDim.x + threadIdx.x;
    if (i >= e) return;
    int s, d;
    if (g_is64) {
        const long long* p = (const long long*)ei;
        s = (int)p[i];
        d = (int)p[(size_t)e + i];
    } else {
        const int* p = (const int*)ei;
        s = p[i];
        d = p[(size_t)e + i];
    }
    g_src[i] = s;
    g_dst[i] = d;
    if ((unsigned)d < NNODES) atomicAdd(&g_deg[d], 1);
}

// Block-level inclusive scan of per-node REAL edge counts (deg-1).
__global__ void k_scan_block(int n) {
    __shared__ int s[1024];
    int i = blockIdx.x * 1024 + threadIdx.x;
    int v = (i < n) ? (g_deg[i] - 1) : 0;
    s[threadIdx.x] = v;
    __syncthreads();
    for (int off = 1; off < 1024; off <<= 1) {
        int t = (threadIdx.x >= off) ? s[threadIdx.x - off] : 0;
        __syncthreads();
        s[threadIdx.x] += t;
        __syncthreads();
    }
    if (i < n) g_rowptr[i] = s[threadIdx.x] - v;
    if (threadIdx.x == 1023) g_bsums[blockIdx.x] = s[1023];
}

// Each block redundantly scans g_bsums (<=128 values) in smem, then applies
// offsets + computes dinv. Replaces the separate k_scan_bsums pass.
__global__ void k_add_off2(int n, int nb) {
    __shared__ int s[128], sx[128];
    int t = threadIdx.x;
    if (t < 128) {
        int v = (t < nb) ? g_bsums[t] : 0;
        s[t] = v;
        sx[t] = v;
    }
    __syncthreads();
    for (int off = 1; off < 128; off <<= 1) {
        int u = 0;
        if (t < 128 && t >= off) u = s[t - off];
        __syncthreads();
        if (t < 128) s[t] += u;
        __syncthreads();
    }
    if (t < 128) sx[t] = s[t] - sx[t];  // exclusive prefix
    __syncthreads();
    int i = blockIdx.x * blockDim.x + t;
    if (i < n) {
        int rp = g_rowptr[i] + sx[i >> 10];
        g_rowptr[i] = rp;
        g_cursor[i] = rp;
        g_dinv[i] = rsqrtf((float)g_deg[i]);
    }
}

__global__ void k_scatter(int e) {
    int i = blockIdx.x * blockDim.x + threadIdx.x;
    if (i < e) {
        unsigned s = (unsigned)g_src[i];
        unsigned d = (unsigned)g_dst[i];
        if (s < NNODES && d < NNODES) {
            int pos = atomicAdd(&g_cursor[d], 1);
            if (pos >= 0 && pos < EMAX) g_col[pos] = (int)s;
        }
    }
}

// ---------------- GEMM: g_h[n,FO] = dinv[row] * (X[n,128] * W[128,FO]) ----------------
// (R8 formulation — fastest measured.) 256 threads, 64-row tile, K-tiled (KC=32),
// FFMA2 inner loop with k-paired x loads. Epilogue pre-scales by dinv[row].
template <int FO, bool X_FROM_G>
__global__ void __launch_bounds__(256) k_gemm(const float* __restrict__ Xin,
                                              const float* __restrict__ W, int n) {
    constexpr int TR  = 64;
    constexpr int KC  = 32;         // k-chunk
    constexpr int CPT = FO / 4;     // threads covering the column dim (4 cols each)
    constexpr int G   = 256 / CPT;  // row groups
    constexpr int RPT = TR / G;     // rows per thread

    __shared__ float Xs[TR * 128];  // 32 KB
    __shared__ float Ws[KC * FO];   // 16 KB (FO=128) / 8 KB (FO=64)

    const float* X = X_FROM_G ? g_x : Xin;
    float* H = g_h;

    int row0 = blockIdx.x * TR;

    // load X tile (zero-pad OOB rows)
    for (int i = threadIdx.x; i < TR * 128 / 4; i += 256) {
        int r  = i >> 5;      // 32 float4 per row
        int c4 = i & 31;
        float4 v = make_float4(0.f, 0.f, 0.f, 0.f);
        if (row0 + r < n)
            v = reinterpret_cast<const float4*>(X + (size_t)(row0 + r) * 128)[c4];
        reinterpret_cast<float4*>(Xs)[i] = v;
    }

    int cq = threadIdx.x % CPT;     // column quad index (4 cols = 2 f32x2)
    int g  = threadIdx.x / CPT;
    int r0 = g * RPT;

    ull acc0[RPT], acc1[RPT];
#pragma unroll
    for (int r = 0; r < RPT; r++) { acc0[r] = 0ull; acc1[r] = 0ull; }

    const ull* ws64 = reinterpret_cast<const ull*>(Ws);

    for (int kc = 0; kc < 128 / KC; kc++) {
        __syncthreads();  // previous Ws readers done (and X tile ready on iter 0)
        for (int i = threadIdx.x; i < KC * FO / 4; i += 256)
            reinterpret_cast<float4*>(Ws)[i] =
                reinterpret_cast<const float4*>(W + (size_t)kc * KC * FO)[i];
        __syncthreads();

#pragma unroll 4
        for (int k2 = 0; k2 < KC; k2 += 2) {
            ull w00 = ws64[(k2 + 0) * (FO / 2) + cq * 2];
            ull w01 = ws64[(k2 + 0) * (FO / 2) + cq * 2 + 1];
            ull w10 = ws64[(k2 + 1) * (FO / 2) + cq * 2];
            ull w11 = ws64[(k2 + 1) * (FO / 2) + cq * 2 + 1];
#pragma unroll
            for (int r = 0; r < RPT; r++) {
                float2 xv = *reinterpret_cast<const float2*>(
                    &Xs[(r0 + r) * 128 + kc * KC + k2]);
                ull x0 = pack2(xv.x);
                ull x1 = pack2(xv.y);
                ffma2(acc0[r], x0, w00);
                ffma2(acc1[r], x0, w01);
                ffma2(acc0[r], x1, w10);
                ffma2(acc1[r], x1, w11);
            }
        }
    }

#pragma unroll
    for (int r = 0; r < RPT; r++) {
        int row = row0 + r0 + r;
        if (row < n) {
            float dv = g_dinv[row];
            float2 a = unpack2(acc0[r]);
            float2 b = unpack2(acc1[r]);
            float4 v = make_float4(a.x * dv, a.y * dv, b.x * dv, b.y * dv);
            reinterpret_cast<float4*>(H + (size_t)row * FO)[cq] = v;
        }
    }
}

// ---------------- Aggregation ----------------
// H is pre-scaled: H'[v] = dinv[v] * (X W)[v].
// out[v] = relu( dinv[v] * (H'[v] + sum_{e: dst=v} H'[src_e]) + b )
template <int FO, bool OUT_TO_G>
__global__ void k_agg(const float* __restrict__ b, float* __restrict__ out_ext, int n) {
    int node = (blockIdx.x * blockDim.x + threadIdx.x) >> 5;
    if (node >= n) return;
    int lane = threadIdx.x & 31;
    constexpr int V = FO / 32;
    int f0 = lane * V;

    const float* H = g_h;
    float* out = OUT_TO_G ? g_x : out_ext;

    float dv = g_dinv[node];
    float acc[V];
    {
        const float* hr = H + (size_t)node * FO + f0;
        if (V == 4) {
            float4 hv = *reinterpret_cast<const float4*>(hr);
            acc[0] = hv.x; acc[1] = hv.y; acc[2] = hv.z; acc[3] = hv.w;
        } else {
            float2 hv = *reinterpret_cast<const float2*>(hr);
            acc[0] = hv.x; acc[1] = hv.y;
        }
    }

    int beg = g_rowptr[node];
    int end = beg + (g_deg[node] - 1);
    int e = beg;
    for (; e + 3 < end; e += 4) {
        int s0 = g_col[e], s1 = g_col[e + 1], s2 = g_col[e + 2], s3 = g_col[e + 3];
        const float* h0 = H + (size_t)s0 * FO + f0;
        const float* h1 = H + (size_t)s1 * FO + f0;
        const float* h2 = H + (size_t)s2 * FO + f0;
        const float* h3 = H + (size_t)s3 * FO + f0;
        if (V == 4) {
            float4 a = *reinterpret_cast<const float4*>(h0);
            float4 c = *reinterpret_cast<const float4*>(h1);
            float4 d = *reinterpret_cast<const float4*>(h2);
            float4 f = *reinterpret_cast<const float4*>(h3);
            acc[0] += (a.x + c.x) + (d.x + f.x);
            acc[1] += (a.y + c.y) + (d.y + f.y);
            acc[2] += (a.z + c.z) + (d.z + f.z);
            acc[3] += (a.w + c.w) + (d.w + f.w);
        } else {
            float2 a = *reinterpret_cast<const float2*>(h0);
            float2 c = *reinterpret_cast<const float2*>(h1);
            float2 d = *reinterpret_cast<const float2*>(h2);
            float2 f = *reinterpret_cast<const float2*>(h3);
            acc[0] += (a.x + c.x) + (d.x + f.x);
            acc[1] += (a.y + c.y) + (d.y + f.y);
        }
    }
    for (; e < end; e++) {
        int s0 = g_col[e];
        const float* h0 = H + (size_t)s0 * FO + f0;
        if (V == 4) {
            float4 a = *reinterpret_cast<const float4*>(h0);
            acc[0] += a.x; acc[1] += a.y; acc[2] += a.z; acc[3] += a.w;
        } else {
            float2 a = *reinterpret_cast<const float2*>(h0);
            acc[0] += a.x; acc[1] += a.y;
        }
    }

    float* orow = out + (size_t)node * FO + f0;
    if (V == 4) {
        float4 v;
        v.x = fmaxf(acc[0] * dv + b[f0 + 0], 0.f);
        v.y = fmaxf(acc[1] * dv + b[f0 + 1], 0.f);
        v.z = fmaxf(acc[2] * dv + b[f0 + 2], 0.f);
        v.w = fmaxf(acc[3] * dv + b[f0 + 3], 0.f);
        *reinterpret_cast<float4*>(orow) = v;
    } else {
        float2 v;
        v.x = fmaxf(acc[0] * dv + b[f0 + 0], 0.f);
        v.y = fmaxf(acc[1] * dv + b[f0 + 1], 0.f);
        *reinterpret_cast<float2*>(orow) = v;
    }
}

// ---------------- launch ----------------

extern "C" void kernel_launch(void* const* d_in, const int* in_sizes, int n_in,
                              void* d_out, int out_size) {
    // Classify inputs by element count — robust to metadata ordering.
    const float* x  = nullptr;
    const void*  ei = nullptr;
    const float* W[4] = {nullptr, nullptr, nullptr, nullptr};
    const float* B[4] = {nullptr, nullptr, nullptr, nullptr};
    int nw = 0, nb_ = 0;
    for (int i = 0; i < n_in; i++) {
        int sz = in_sizes[i];
        if (sz == NNODES * FDIM)       x = (const float*)d_in[i];
        else if (sz == 2 * EMAX)       ei = d_in[i];
        else if (sz == 128 * 128)      { if (nw < 3) W[nw++] = (const float*)d_in[i]; }
        else if (sz == 128 * 64)       W[3] = (const float*)d_in[i];
        else if (sz == 128)            { if (nb_ < 3) B[nb_++] = (const float*)d_in[i]; }
        else if (sz == 64)             B[3] = (const float*)d_in[i];
    }

    const int n = NNODES;
    const int E = EMAX;
    float* Obuf = (float*)d_out;

    // ---- CSR build (5 launches) ----
    k_init_detect<<<(n + 255) / 256, 256>>>((const int*)ei, n);
    k_decode_hist<<<(E + 255) / 256, 256>>>(ei, E);
    int nblk = (n + 1023) / 1024;
    k_scan_block<<<nblk, 1024>>>(n);
    k_add_off2<<<(n + 255) / 256, 256>>>(n, nblk);
    k_scatter<<<(E + 255) / 256, 256>>>(E);

    // ---- layers (launch #6 = k_gemm<128> -> ncu -s 5 captures it) ----
    const int gemm_blocks = (n + 63) / 64;
    const int agg_blocks  = (n * 32 + 255) / 256;

    // L0: x -> g_h -> g_x
    k_gemm<128, false><<<gemm_blocks, 256>>>(x, W[0], n);
    k_agg<128, true><<<agg_blocks, 256>>>(B[0], Obuf, n);
    // L1
    k_gemm<128, true><<<gemm_blocks, 256>>>(x, W[1], n);
    k_agg<128, true><<<agg_blocks, 256>>>(B[1], Obuf, n);
    // L2
    k_gemm<128, true><<<gemm_blocks, 256>>>(x, W[2], n);
    k_agg<128, true><<<agg_blocks, 256>>>(B[2], Obuf, n);
    // L3: 128 -> 64, write straight to d_out
    k_gemm<64, true><<<gemm_blocks, 256>>>(x, W[3], n);
    k_agg<64, false><<<agg_blocks, 256>>>(B[3], Obuf, n);
}

// round 14
// speedup vs baseline: 1.3729x; 1.0162x over previous
#include <cuda_runtime.h>
#include <cstddef>
#include <cstdint>

// Problem constants (fixed by the reference)
#define NNODES 100000
#define EMAX   1600000
#define FDIM   128

typedef unsigned long long ull;

// ---------------- scratch (static device globals; no runtime alloc) ----------------
__device__ int   g_is64;                   // edge_index dtype flag (1 = int64)
__device__ int   g_src[EMAX];              // decoded src indices (int32)
__device__ int   g_dst[EMAX];              // decoded dst indices (int32)
__device__ int   g_deg[NNODES];            // in-degree incl. self loop
__device__ float g_dinv[NNODES];           // deg^-1/2
__device__ int   g_rowptr[NNODES];         // CSR row start (real edges only)
__device__ int   g_cursor[NNODES];         // scatter cursors
__device__ int   g_col[EMAX];              // CSR column (src) per edge
__device__ int   g_bsums[128];             // block sums for scan
__device__ float g_h[(size_t)NNODES * FDIM];   // per-layer GEMM output (pre-scaled by dinv)
__device__ float g_x[(size_t)NNODES * FDIM];   // per-layer activation ping buffer

// ---------------- packed f32x2 helpers (FFMA2 path, works on sm_100) ----------------

__device__ __forceinline__ void ffma2(ull& d, ull a, ull b) {
    asm("fma.rn.f32x2 %0, %1, %2, %0;" : "+l"(d) : "l"(a), "l"(b));
}

__device__ __forceinline__ ull pack2(float x) {
    ull r;
    unsigned xi = __float_as_uint(x);
    asm("mov.b64 %0, {%1, %1};" : "=l"(r) : "r"(xi));
    return r;
}

__device__ __forceinline__ float2 unpack2(ull v) {
    unsigned lo, hi;
    asm("mov.b64 {%0, %1}, %2;" : "=r"(lo), "=r"(hi) : "l"(v));
    return make_float2(__uint_as_float(lo), __uint_as_float(hi));
}

// ---------------- CSR build ----------------

// init deg=1 everywhere; block 0 also detects edge dtype.
__global__ void k_init_detect(const int* __restrict__ ei32, int n) {
    __shared__ int nz;
    int i = blockIdx.x * blockDim.x + threadIdx.x;
    if (i < n) g_deg[i] = 1;  // self loop
    if (blockIdx.x == 0) {
        if (threadIdx.x == 0) nz = 0;
        __syncthreads();
        for (int j = threadIdx.x; j < 4096; j += 256)
            if (ei32[2 * j + 1] != 0) atomicAdd(&nz, 1);
        __syncthreads();
        if (threadIdx.x == 0) g_is64 = (nz == 0) ? 1 : 0;
    }
}

// Decode edge indices (int32 or int64) AND histogram dst degrees in one pass.
__global__ void k_decode_hist(const void* __restrict__ ei, int e) {
    int i = blockIdx.x * blockDim.x + threadIdx.x;
    if (i >= e) return;
    int s, d;
    if (g_is64) {
        const long long* p = (const long long*)ei;
        s = (int)p[i];
        d = (int)p[(size_t)e + i];
    } else {
        const int* p = (const int*)ei;
        s = p[i];
        d = p[(size_t)e + i];
    }
    g_src[i] = s;
    g_dst[i] = d;
    if ((unsigned)d < NNODES) atomicAdd(&g_deg[d], 1);
}

// Block-level inclusive scan of per-node REAL edge counts (deg-1).
// deg is final here, so also compute dinv (needed by GEMM L0, launch #4).
__global__ void k_scan_block(int n) {
    __shared__ int s[1024];
    int i = blockIdx.x * 1024 + threadIdx.x;
    int v = (i < n) ? (g_deg[i] - 1) : 0;
    s[threadIdx.x] = v;
    __syncthreads();
    for (int off = 1; off < 1024; off <<= 1) {
        int t = (threadIdx.x >= off) ? s[threadIdx.x - off] : 0;
        __syncthreads();
        s[threadIdx.x] += t;
        __syncthreads();
    }
    if (i < n) {
        g_rowptr[i] = s[threadIdx.x] - v;
        g_dinv[i] = rsqrtf((float)(v + 1));
    }
    if (threadIdx.x == 1023) g_bsums[blockIdx.x] = s[1023];
}

// Each block redundantly scans g_bsums (<=128 values) in smem, then applies offsets.
__global__ void k_add_off2(int n, int nb) {
    __shared__ int s[128], sx[128];
    int t = threadIdx.x;
    if (t < 128) {
        int v = (t < nb) ? g_bsums[t] : 0;
        s[t] = v;
        sx[t] = v;
    }
    __syncthreads();
    for (int off = 1; off < 128; off <<= 1) {
        int u = 0;
        if (t < 128 && t >= off) u = s[t - off];
        __syncthreads();
        if (t < 128) s[t] += u;
        __syncthreads();
    }
    if (t < 128) sx[t] = s[t] - sx[t];  // exclusive prefix
    __syncthreads();
    int i = blockIdx.x * blockDim.x + t;
    if (i < n) {
        int rp = g_rowptr[i] + sx[i >> 10];
        g_rowptr[i] = rp;
        g_cursor[i] = rp;
    }
}

__global__ void k_scatter(int e) {
    int i = blockIdx.x * blockDim.x + threadIdx.x;
    if (i < e) {
        unsigned s = (unsigned)g_src[i];
        unsigned d = (unsigned)g_dst[i];
        if (s < NNODES && d < NNODES) {
            int pos = atomicAdd(&g_cursor[d], 1);
            if (pos >= 0 && pos < EMAX) g_col[pos] = (int)s;
        }
    }
}

// ---------------- GEMM: g_h[n,FO] = dinv[row] * (X[n,128] * W[128,FO]) ----------------
// (R8 formulation — fastest measured.) 256 threads, 64-row tile, K-tiled (KC=32),
// FFMA2 inner loop with k-paired x loads. Epilogue pre-scales by dinv[row].
template <int FO, bool X_FROM_G>
__global__ void __launch_bounds__(256) k_gemm(const float* __restrict__ Xin,
                                              const float* __restrict__ W, int n) {
    constexpr int TR  = 64;
    constexpr int KC  = 32;         // k-chunk
    constexpr int CPT = FO / 4;     // threads covering the column dim (4 cols each)
    constexpr int G   = 256 / CPT;  // row groups
    constexpr int RPT = TR / G;     // rows per thread

    __shared__ float Xs[TR * 128];  // 32 KB
    __shared__ float Ws[KC * FO];   // 16 KB (FO=128) / 8 KB (FO=64)

    const float* X = X_FROM_G ? g_x : Xin;
    float* H = g_h;

    int row0 = blockIdx.x * TR;

    // load X tile (zero-pad OOB rows)
    for (int i = threadIdx.x; i < TR * 128 / 4; i += 256) {
        int r  = i >> 5;      // 32 float4 per row
        int c4 = i & 31;
        float4 v = make_float4(0.f, 0.f, 0.f, 0.f);
        if (row0 + r < n)
            v = reinterpret_cast<const float4*>(X + (size_t)(row0 + r) * 128)[c4];
        reinterpret_cast<float4*>(Xs)[i] = v;
    }

    int cq = threadIdx.x % CPT;     // column quad index (4 cols = 2 f32x2)
    int g  = threadIdx.x / CPT;
    int r0 = g * RPT;

    ull acc0[RPT], acc1[RPT];
#pragma unroll
    for (int r = 0; r < RPT; r++) { acc0[r] = 0ull; acc1[r] = 0ull; }

    const ull* ws64 = reinterpret_cast<const ull*>(Ws);

    for (int kc = 0; kc < 128 / KC; kc++) {
        __syncthreads();  // previous Ws readers done (and X tile ready on iter 0)
        for (int i = threadIdx.x; i < KC * FO / 4; i += 256)
            reinterpret_cast<float4*>(Ws)[i] =
                reinterpret_cast<const float4*>(W + (size_t)kc * KC * FO)[i];
        __syncthreads();

#pragma unroll 4
        for (int k2 = 0; k2 < KC; k2 += 2) {
            ull w00 = ws64[(k2 + 0) * (FO / 2) + cq * 2];
            ull w01 = ws64[(k2 + 0) * (FO / 2) + cq * 2 + 1];
            ull w10 = ws64[(k2 + 1) * (FO / 2) + cq * 2];
            ull w11 = ws64[(k2 + 1) * (FO / 2) + cq * 2 + 1];
#pragma unroll
            for (int r = 0; r < RPT; r++) {
                float2 xv = *reinterpret_cast<const float2*>(
                    &Xs[(r0 + r) * 128 + kc * KC + k2]);
                ull x0 = pack2(xv.x);
                ull x1 = pack2(xv.y);
                ffma2(acc0[r], x0, w00);
                ffma2(acc1[r], x0, w01);
                ffma2(acc0[r], x1, w10);
                ffma2(acc1[r], x1, w11);
            }
        }
    }

#pragma unroll
    for (int r = 0; r < RPT; r++) {
        int row = row0 + r0 + r;
        if (row < n) {
            float dv = g_dinv[row];
            float2 a = unpack2(acc0[r]);
            float2 b = unpack2(acc1[r]);
            float4 v = make_float4(a.x * dv, a.y * dv, b.x * dv, b.y * dv);
            reinterpret_cast<float4*>(H + (size_t)row * FO)[cq] = v;
        }
    }
}

// ---------------- Aggregation ----------------
// H is pre-scaled: H'[v] = dinv[v] * (X W)[v].
// out[v] = relu( dinv[v] * (H'[v] + sum_{e: dst=v} H'[src_e]) + b )
// One warp per node; 8-way edge unroll for gather MLP.
template <int FO, bool OUT_TO_G>
__global__ void k_agg(const float* __restrict__ b, float* __restrict__ out_ext, int n) {
    int node = (blockIdx.x * blockDim.x + threadIdx.x) >> 5;
    if (node >= n) return;
    int lane = threadIdx.x & 31;
    constexpr int V = FO / 32;
    int f0 = lane * V;

    const float* H = g_h;
    float* out = OUT_TO_G ? g_x : out_ext;

    float dv = g_dinv[node];
    float acc[V];
    {
        const float* hr = H + (size_t)node * FO + f0;
        if (V == 4) {
            float4 hv = *reinterpret_cast<const float4*>(hr);
            acc[0] = hv.x; acc[1] = hv.y; acc[2] = hv.z; acc[3] = hv.w;
        } else {
            float2 hv = *reinterpret_cast<const float2*>(hr);
            acc[0] = hv.x; acc[1] = hv.y;
        }
    }

    int beg = g_rowptr[node];
    int end = beg + (g_deg[node] - 1);
    int e = beg;
    // 8-way unroll for gather MLP
    for (; e + 7 < end; e += 8) {
        const float* hp[8];
#pragma unroll
        for (int j = 0; j < 8; j++)
            hp[j] = H + (size_t)g_col[e + j] * FO + f0;
        if (V == 4) {
            float4 t0 = *reinterpret_cast<const float4*>(hp[0]);
            float4 t1 = *reinterpret_cast<const float4*>(hp[1]);
            float4 t2 = *reinterpret_cast<const float4*>(hp[2]);
            float4 t3 = *reinterpret_cast<const float4*>(hp[3]);
            float4 t4 = *reinterpret_cast<const float4*>(hp[4]);
            float4 t5 = *reinterpret_cast<const float4*>(hp[5]);
            float4 t6 = *reinterpret_cast<const float4*>(hp[6]);
            float4 t7 = *reinterpret_cast<const float4*>(hp[7]);
            acc[0] += ((t0.x + t1.x) + (t2.x + t3.x)) + ((t4.x + t5.x) + (t6.x + t7.x));
            acc[1] += ((t0.y + t1.y) + (t2.y + t3.y)) + ((t4.y + t5.y) + (t6.y + t7.y));
            acc[2] += ((t0.z + t1.z) + (t2.z + t3.z)) + ((t4.z + t5.z) + (t6.z + t7.z));
            acc[3] += ((t0.w + t1.w) + (t2.w + t3.w)) + ((t4.w + t5.w) + (t6.w + t7.w));
        } else {
            float2 t0 = *reinterpret_cast<const float2*>(hp[0]);
            float2 t1 = *reinterpret_cast<const float2*>(hp[1]);
            float2 t2 = *reinterpret_cast<const float2*>(hp[2]);
            float2 t3 = *reinterpret_cast<const float2*>(hp[3]);
            float2 t4 = *reinterpret_cast<const float2*>(hp[4]);
            float2 t5 = *reinterpret_cast<const float2*>(hp[5]);
            float2 t6 = *reinterpret_cast<const float2*>(hp[6]);
            float2 t7 = *reinterpret_cast<const float2*>(hp[7]);
            acc[0] += ((t0.x + t1.x) + (t2.x + t3.x)) + ((t4.x + t5.x) + (t6.x + t7.x));
            acc[1] += ((t0.y + t1.y) + (t2.y + t3.y)) + ((t4.y + t5.y) + (t6.y + t7.y));
        }
    }
    for (; e < end; e++) {
        int s0 = g_col[e];
        const float* h0 = H + (size_t)s0 * FO + f0;
        if (V == 4) {
            float4 a = *reinterpret_cast<const float4*>(h0);
            acc[0] += a.x; acc[1] += a.y; acc[2] += a.z; acc[3] += a.w;
        } else {
            float2 a = *reinterpret_cast<const float2*>(h0);
            acc[0] += a.x; acc[1] += a.y;
        }
    }

    float* orow = out + (size_t)node * FO + f0;
    if (V == 4) {
        float4 v;
        v.x = fmaxf(acc[0] * dv + b[f0 + 0], 0.f);
        v.y = fmaxf(acc[1] * dv + b[f0 + 1], 0.f);
        v.z = fmaxf(acc[2] * dv + b[f0 + 2], 0.f);
        v.w = fmaxf(acc[3] * dv + b[f0 + 3], 0.f);
        *reinterpret_cast<float4*>(orow) = v;
    } else {
        float2 v;
        v.x = fmaxf(acc[0] * dv + b[f0 + 0], 0.f);
        v.y = fmaxf(acc[1] * dv + b[f0 + 1], 0.f);
        *reinterpret_cast<float2*>(orow) = v;
    }
}

// ---------------- launch ----------------

extern "C" void kernel_launch(void* const* d_in, const int* in_sizes, int n_in,
                              void* d_out, int out_size) {
    // Classify inputs by element count — robust to metadata ordering.
    const float* x  = nullptr;
    const void*  ei = nullptr;
    const float* W[4] = {nullptr, nullptr, nullptr, nullptr};
    const float* B[4] = {nullptr, nullptr, nullptr, nullptr};
    int nw = 0, nb_ = 0;
    for (int i = 0; i < n_in; i++) {
        int sz = in_sizes[i];
        if (sz == NNODES * FDIM)       x = (const float*)d_in[i];
        else if (sz == 2 * EMAX)       ei = d_in[i];
        else if (sz == 128 * 128)      { if (nw < 3) W[nw++] = (const float*)d_in[i]; }
        else if (sz == 128 * 64)       W[3] = (const float*)d_in[i];
        else if (sz == 128)            { if (nb_ < 3) B[nb_++] = (const float*)d_in[i]; }
        else if (sz == 64)             B[3] = (const float*)d_in[i];
    }

    const int n = NNODES;
    const int E = EMAX;
    float* Obuf = (float*)d_out;

    const int gemm_blocks = (n + 63) / 64;
    const int agg_blocks  = (n * 32 + 255) / 256;
    int nblk = (n + 1023) / 1024;

    // ---- CSR build, interleaved so launch #4 is k_gemm<128> (ncu captures #4) ----
    k_init_detect<<<(n + 255) / 256, 256>>>((const int*)ei, n);   // 1
    k_decode_hist<<<(E + 255) / 256, 256>>>(ei, E);               // 2 (deg final after this)
    k_scan_block<<<nblk, 1024>>>(n);                              // 3 (also computes dinv)
    // GEMM L0 needs only x, W0, dinv — independent of CSR scatter.
    k_gemm<128, false><<<gemm_blocks, 256>>>(x, W[0], n);         // 4  <- profiled
    k_add_off2<<<(n + 255) / 256, 256>>>(n, nblk);                // 5
    k_scatter<<<(E + 255) / 256, 256>>>(E);                       // 6

    // ---- layers ----
    k_agg<128, true><<<agg_blocks, 256>>>(B[0], Obuf, n);
    k_gemm<128, true><<<gemm_blocks, 256>>>(x, W[1], n);
    k_agg<128, true><<<agg_blocks, 256>>>(B[1], Obuf, n);
    k_gemm<128, true><<<gemm_blocks, 256>>>(x, W[2], n);
    k_agg<128, true><<<agg_blocks, 256>>>(B[2], Obuf, n);
    k_gemm<64, true><<<gemm_blocks, 256>>>(x, W[3], n);
    k_agg<64, false><<<agg_blocks, 256>>>(B[3], Obuf, n);
}